// round 1
// baseline (speedup 1.0000x reference)
#include <cuda_runtime.h>
#include <math.h>

#define NB    4
#define CCH   512
#define HW    4096
#define NGRP  32
#define CPG   (CCH / NGRP)     /* 16 */
#define D3    (3 * CCH)        /* 1536 */
#define SEQ   HW

/* ---- scratch (allocation-free rule: __device__ globals) ---- */
__device__ float g_xn    [(size_t)NB * CCH * HW];      /*  33.5 MB */
__device__ float g_qkv   [(size_t)NB * D3  * HW];      /* 100.7 MB */
__device__ float g_scores[(size_t)NB * SEQ * SEQ];     /* 268.4 MB */
__device__ float g_att   [(size_t)NB * CCH * HW];      /*  33.5 MB */

/* =================== GroupNorm =================== */
/* one block per (n, group); group = 16 channels x 4096 elems */
__global__ __launch_bounds__(256) void gn_kernel(
    const float* __restrict__ x,
    const float* __restrict__ gamma,
    const float* __restrict__ beta)
{
    const int g   = blockIdx.x;          /* 0..127 */
    const int n   = g / NGRP;
    const int grp = g % NGRP;
    const float* xp = x    + ((size_t)n * CCH + (size_t)grp * CPG) * HW;
    float*       op = g_xn + ((size_t)n * CCH + (size_t)grp * CPG) * HW;
    const int NE = CPG * HW;             /* 65536 */

    float s = 0.f, ss = 0.f;
    for (int i = threadIdx.x; i < NE; i += 256) {
        float v = xp[i];
        s  += v;
        ss += v * v;
    }
    __shared__ float rs[256], rss[256];
    rs[threadIdx.x] = s; rss[threadIdx.x] = ss;
    __syncthreads();
    for (int o = 128; o > 0; o >>= 1) {
        if (threadIdx.x < o) {
            rs [threadIdx.x] += rs [threadIdx.x + o];
            rss[threadIdx.x] += rss[threadIdx.x + o];
        }
        __syncthreads();
    }
    const float mean = rs[0] * (1.0f / NE);
    const float var  = rss[0] * (1.0f / NE) - mean * mean;
    const float rstd = rsqrtf(var + 1e-5f);

    for (int i = threadIdx.x; i < NE; i += 256) {
        int ch = grp * CPG + (i >> 12);  /* i / HW */
        op[i] = (xp[i] - mean) * rstd * gamma[ch] + beta[ch];
    }
}

/* =================== NN SGEMM ===================
 * C[m,n] = sum_k A[m,k] * B[k,n]   (+bias[m], optional +R[m,n])
 * A: row-major [M,K] (shared across batch); B,C,R: per-batch [.,N], N=4096
 * 128x128 block tile, BK=8, 8x8 per thread, 256 threads
 */
template <bool RES>
__global__ __launch_bounds__(256) void sgemm_nn(
    const float* __restrict__ A, const float* __restrict__ Bsrc,
    float* __restrict__ Csrc,
    const float* __restrict__ bias, const float* __restrict__ Rsrc,
    int M, int K)
{
    const int N = HW;
    const int z = blockIdx.z;
    const float* B = Bsrc + (size_t)z * K * N;
    float*       Cp = Csrc + (size_t)z * M * N;
    const float* R  = RES ? (Rsrc + (size_t)z * M * N) : nullptr;

    __shared__ float As[8][128];
    __shared__ float Bs[8][128];

    const int t  = threadIdx.x;
    const int tx = t & 15, ty = t >> 4;
    const int m0 = blockIdx.y * 128, n0 = blockIdx.x * 128;

    const int aRow = t >> 1, aCol = (t & 1) * 4;   /* A tile 128x8 */
    const int bRow = t >> 5, bCol = (t & 31) * 4;  /* B tile 8x128 */

    float acc[8][8] = {};

    for (int k0 = 0; k0 < K; k0 += 8) {
        float4 av = *(const float4*)&A[(size_t)(m0 + aRow) * K + k0 + aCol];
        float4 bv = *(const float4*)&B[(size_t)(k0 + bRow) * N + n0 + bCol];
        As[aCol + 0][aRow] = av.x;
        As[aCol + 1][aRow] = av.y;
        As[aCol + 2][aRow] = av.z;
        As[aCol + 3][aRow] = av.w;
        *(float4*)&Bs[bRow][bCol] = bv;
        __syncthreads();
#pragma unroll
        for (int k = 0; k < 8; k++) {
            float a[8], b[8];
#pragma unroll
            for (int i = 0; i < 8; i++) a[i] = As[k][ty * 8 + i];
#pragma unroll
            for (int j = 0; j < 8; j++) b[j] = Bs[k][tx * 8 + j];
#pragma unroll
            for (int i = 0; i < 8; i++)
#pragma unroll
                for (int j = 0; j < 8; j++) acc[i][j] += a[i] * b[j];
        }
        __syncthreads();
    }

#pragma unroll
    for (int i = 0; i < 8; i++) {
        const int m = m0 + ty * 8 + i;
        const float bi = bias[m];
#pragma unroll
        for (int j = 0; j < 8; j++) {
            const int n = n0 + tx * 8 + j;
            float v = acc[i][j] + bi;
            if (RES) v += R[(size_t)m * N + n];
            Cp[(size_t)m * N + n] = v;
        }
    }
}

/* =================== TN SGEMM (scores) ===================
 * C[s,t] = scale * sum_c Q[c,s] * K[c,t]
 * Q = g_qkv[z][0:512, :], K = g_qkv[z][512:1024, :]; C = g_scores[z]
 */
__global__ __launch_bounds__(256) void sgemm_tn_scores()
{
    const int Kd = CCH;
    const int z  = blockIdx.z;
    const float* A = g_qkv + (size_t)z * D3 * HW;                     /* Q */
    const float* B = g_qkv + (size_t)z * D3 * HW + (size_t)CCH * HW;  /* K */
    float* Cp = g_scores + (size_t)z * SEQ * SEQ;

    __shared__ float As[8][128];
    __shared__ float Bs[8][128];

    const int t  = threadIdx.x;
    const int tx = t & 15, ty = t >> 4;
    const int m0 = blockIdx.y * 128, n0 = blockIdx.x * 128;
    const int r  = t >> 5, c4 = (t & 31) * 4;   /* 8x128 tiles, m/n contiguous */

    float acc[8][8] = {};

    for (int k0 = 0; k0 < Kd; k0 += 8) {
        float4 av = *(const float4*)&A[(size_t)(k0 + r) * HW + m0 + c4];
        float4 bv = *(const float4*)&B[(size_t)(k0 + r) * HW + n0 + c4];
        *(float4*)&As[r][c4] = av;
        *(float4*)&Bs[r][c4] = bv;
        __syncthreads();
#pragma unroll
        for (int k = 0; k < 8; k++) {
            float a[8], b[8];
#pragma unroll
            for (int i = 0; i < 8; i++) a[i] = As[k][ty * 8 + i];
#pragma unroll
            for (int j = 0; j < 8; j++) b[j] = Bs[k][tx * 8 + j];
#pragma unroll
            for (int i = 0; i < 8; i++)
#pragma unroll
                for (int j = 0; j < 8; j++) acc[i][j] += a[i] * b[j];
        }
        __syncthreads();
    }

    const float scale = 0.044194173824159216f;  /* 1/sqrt(512) */
#pragma unroll
    for (int i = 0; i < 8; i++) {
        const int m = m0 + ty * 8 + i;
#pragma unroll
        for (int j = 0; j < 8; j++) {
            const int n = n0 + tx * 8 + j;
            Cp[(size_t)m * SEQ + n] = acc[i][j] * scale;
        }
    }
}

/* =================== row softmax over scores =================== */
__global__ __launch_bounds__(256) void softmax_rows()
{
    float* p = g_scores + (size_t)blockIdx.x * SEQ;
    __shared__ float red[256];

    float m = -1e30f;
    for (int i = threadIdx.x; i < SEQ; i += 256) m = fmaxf(m, p[i]);
    red[threadIdx.x] = m;
    __syncthreads();
    for (int o = 128; o > 0; o >>= 1) {
        if (threadIdx.x < o)
            red[threadIdx.x] = fmaxf(red[threadIdx.x], red[threadIdx.x + o]);
        __syncthreads();
    }
    m = red[0];
    __syncthreads();

    float s = 0.f;
    for (int i = threadIdx.x; i < SEQ; i += 256) {
        float e = __expf(p[i] - m);
        p[i] = e;
        s += e;
    }
    red[threadIdx.x] = s;
    __syncthreads();
    for (int o = 128; o > 0; o >>= 1) {
        if (threadIdx.x < o) red[threadIdx.x] += red[threadIdx.x + o];
        __syncthreads();
    }
    const float inv = 1.0f / red[0];
    for (int i = threadIdx.x; i < SEQ; i += 256) p[i] *= inv;
}

/* =================== NT SGEMM (PV) ===================
 * C[c,s] = sum_t V[c,t] * P[s,t]
 * A = V = g_qkv[z][1024:1536, :] (M=512, K=4096, k-contig)
 * B = P = g_scores[z]            (N=4096, K=4096, k-contig)
 */
__global__ __launch_bounds__(256) void sgemm_nt_pv()
{
    const int Kd = SEQ;
    const int z  = blockIdx.z;
    const float* A = g_qkv + (size_t)z * D3 * HW + 2 * (size_t)CCH * HW; /* V */
    const float* B = g_scores + (size_t)z * SEQ * SEQ;                   /* P */
    float* Cp = g_att + (size_t)z * CCH * HW;

    __shared__ float As[8][128];
    __shared__ float Bs[8][128];

    const int t  = threadIdx.x;
    const int tx = t & 15, ty = t >> 4;
    const int m0 = blockIdx.y * 128, n0 = blockIdx.x * 128;
    const int row = t >> 1, col = (t & 1) * 4;   /* both tiles 128x8, transpose-store */

    float acc[8][8] = {};

    for (int k0 = 0; k0 < Kd; k0 += 8) {
        float4 av = *(const float4*)&A[(size_t)(m0 + row) * Kd + k0 + col];
        float4 bv = *(const float4*)&B[(size_t)(n0 + row) * Kd + k0 + col];
        As[col + 0][row] = av.x; As[col + 1][row] = av.y;
        As[col + 2][row] = av.z; As[col + 3][row] = av.w;
        Bs[col + 0][row] = bv.x; Bs[col + 1][row] = bv.y;
        Bs[col + 2][row] = bv.z; Bs[col + 3][row] = bv.w;
        __syncthreads();
#pragma unroll
        for (int k = 0; k < 8; k++) {
            float a[8], b[8];
#pragma unroll
            for (int i = 0; i < 8; i++) a[i] = As[k][ty * 8 + i];
#pragma unroll
            for (int j = 0; j < 8; j++) b[j] = Bs[k][tx * 8 + j];
#pragma unroll
            for (int i = 0; i < 8; i++)
#pragma unroll
                for (int j = 0; j < 8; j++) acc[i][j] += a[i] * b[j];
        }
        __syncthreads();
    }

#pragma unroll
    for (int i = 0; i < 8; i++) {
        const int m = m0 + ty * 8 + i;
#pragma unroll
        for (int j = 0; j < 8; j++) {
            const int n = n0 + tx * 8 + j;
            Cp[(size_t)m * HW + n] = acc[i][j];
        }
    }
}

/* =================== launch =================== */
extern "C" void kernel_launch(void* const* d_in, const int* in_sizes, int n_in,
                              void* d_out, int out_size)
{
    const float* x     = (const float*)d_in[0];
    const float* gns   = (const float*)d_in[1];
    const float* gnb   = (const float*)d_in[2];
    const float* w_in  = (const float*)d_in[3];
    const float* b_in  = (const float*)d_in[4];
    const float* w_out = (const float*)d_in[5];
    const float* b_out = (const float*)d_in[6];
    float* out = (float*)d_out;

    float *xn_p, *qkv_p, *att_p;
    cudaGetSymbolAddress((void**)&xn_p,  g_xn);
    cudaGetSymbolAddress((void**)&qkv_p, g_qkv);
    cudaGetSymbolAddress((void**)&att_p, g_att);

    /* 1. GroupNorm -> g_xn [n, c, hw] */
    gn_kernel<<<NB * NGRP, 256>>>(x, gns, gnb);

    /* 2. QKV: g_qkv[z][d,s] = w_in[d,:] . g_xn[z][:,s] + b_in[d] */
    {
        dim3 grid(HW / 128, D3 / 128, NB);
        sgemm_nn<false><<<grid, 256>>>(w_in, xn_p, qkv_p, b_in, nullptr, D3, CCH);
    }

    /* 3. scores = scale * Q^T K */
    {
        dim3 grid(SEQ / 128, SEQ / 128, NB);
        sgemm_tn_scores<<<grid, 256>>>();
    }

    /* 4. softmax over t */
    softmax_rows<<<NB * SEQ, 256>>>();

    /* 5. attn @ V -> g_att [c, s] */
    {
        dim3 grid(HW / 128, CCH / 128, NB);
        sgemm_nt_pv<<<grid, 256>>>();
    }

    /* 6. out-proj + bias + residual -> d_out */
    {
        dim3 grid(HW / 128, CCH / 128, NB);
        sgemm_nn<true><<<grid, 256>>>(w_out, att_p, out, b_out, x, CCH, CCH);
    }
}

// round 3
// speedup vs baseline: 2.1804x; 2.1804x over previous
#include <cuda_runtime.h>
#include <cstdint>
#include <math.h>

#define NB    4
#define CCH   512
#define HW    4096
#define NGRP  32
#define CPG   16
#define D3    1536
#define SEQ   4096

#define BM 128
#define BN 128
#define BK 32

/* ---------------- scratch ---------------- */
__device__ float g_seq   [(size_t)NB * HW * CCH];    /* [z][s][c] */
__device__ float g_qkv   [(size_t)NB * HW * D3];     /* [z][s][d] */
__device__ float g_scores[(size_t)NB * SEQ * SEQ];   /* [z][s][t] */
__device__ float g_vt    [(size_t)NB * CCH * HW];    /* [z][c][t] */
__device__ float g_att   [(size_t)NB * HW * CCH];    /* [z][s][c] */
__device__ float g_proj  [(size_t)NB * HW * CCH];    /* [z][s][c] */

/* ---------------- helpers ---------------- */
__device__ __forceinline__ uint32_t smem_u32(const void* p) {
    uint32_t a;
    asm("{ .reg .u64 t; cvta.to.shared.u64 t, %1; cvt.u32.u64 %0, t; }"
        : "=r"(a) : "l"(p));
    return a;
}
__device__ __forceinline__ uint32_t prmt7632(uint32_t a, uint32_t b) {
    uint32_t d;
    asm("prmt.b32 %0, %1, %2, 0x7632;" : "=r"(d) : "r"(a), "r"(b));
    return d;
}
/* pack two f32 -> bf16x2; 'he' goes to upper half, 'le' to lower */
__device__ __forceinline__ uint32_t cvt2(float he, float le) {
    uint32_t d;
    asm("cvt.rn.bf16x2.f32 %0, %1, %2;" : "=r"(d) : "f"(he), "f"(le));
    return d;
}
__device__ __forceinline__ void ldsm4(uint32_t* r, uint32_t addr) {
    asm volatile("ldmatrix.sync.aligned.m8n8.x4.shared.b16 {%0,%1,%2,%3}, [%4];"
        : "=r"(r[0]), "=r"(r[1]), "=r"(r[2]), "=r"(r[3]) : "r"(addr));
}
__device__ __forceinline__ void ldsm2(uint32_t* r, uint32_t addr) {
    asm volatile("ldmatrix.sync.aligned.m8n8.x2.shared.b16 {%0,%1}, [%2];"
        : "=r"(r[0]), "=r"(r[1]) : "r"(addr));
}
__device__ __forceinline__ void mma16816(float* c, const uint32_t* a, const uint32_t* b) {
    asm volatile("mma.sync.aligned.m16n8k16.row.col.f32.bf16.bf16.f32 "
        "{%0,%1,%2,%3}, {%4,%5,%6,%7}, {%8,%9}, {%0,%1,%2,%3};"
        : "+f"(c[0]), "+f"(c[1]), "+f"(c[2]), "+f"(c[3])
        : "r"(a[0]), "r"(a[1]), "r"(a[2]), "r"(a[3]), "r"(b[0]), "r"(b[1]));
}

/* smem layout constants: 4 bf16 tiles [128][32], 80B padded rows */
#define ROWB      80
#define TILE_B    (128 * ROWB)            /* 10240 */
#define STAGE_B   (4 * TILE_B)            /* 40960: Ahi, Alo, Bhi, Blo */
#define GEMM_SMEM (2 * STAGE_B + 1024)    /* + bias/pad */

/* ============ bf16-split GEMM: C[M,N] = A[M,K] . B[N,K]^T ============
 * Both operands K-major fp32.  MODE: 0 plain, 1 +bias[n], 2 *scale.
 */
template <int MODE>
__global__ __launch_bounds__(256, 1)
void gemm_mma(const float* __restrict__ A, const float* __restrict__ B,
              float* __restrict__ C, const float* __restrict__ bias,
              int K, int lda, int ldb, int ldc,
              size_t Abs, size_t Bbs, size_t Cbs)
{
    extern __shared__ char sm[];
    float* sbias = (float*)(sm + 2 * STAGE_B);
    const uint32_t sb = smem_u32(sm);

    const int t = threadIdx.x, wid = t >> 5, lid = t & 31;
    const int wm = wid >> 2, wn = wid & 3;            /* 2 x 4 warp grid */
    const int m0 = blockIdx.y * BM, n0 = blockIdx.x * BN, z = blockIdx.z;

    if (MODE == 1 && t < 128) sbias[t] = bias[n0 + t];

    const float* Ag = A + z * Abs + (size_t)(m0 + (t >> 1)) * lda + (t & 1) * 4;
    const float* Bg = B + z * Bbs + (size_t)(n0 + (t >> 1)) * ldb + (t & 1) * 4;
    const int nch = K / BK;

    float4 av[4], bv[4];
#pragma unroll
    for (int j = 0; j < 4; j++) {
        av[j] = *(const float4*)(Ag + 8 * j);
        bv[j] = *(const float4*)(Bg + 8 * j);
    }

    float acc[4][4][4];
#pragma unroll
    for (int a = 0; a < 4; a++)
#pragma unroll
        for (int b = 0; b < 4; b++)
#pragma unroll
            for (int q = 0; q < 4; q++) acc[a][b][q] = 0.f;

    const uint32_t sbase = (uint32_t)(t >> 1) * ROWB + (uint32_t)(t & 1) * 8u;

    for (int i = 0; i < nch; i++) {
        char* st = sm + (i & 1) * STAGE_B;
        /* convert + store stage */
#pragma unroll
        for (int j = 0; j < 4; j++) {
            {
                float4 v = av[j];
                uint32_t xu = __float_as_uint(v.x), yu = __float_as_uint(v.y);
                uint32_t zu = __float_as_uint(v.z), wu = __float_as_uint(v.w);
                uint32_t h0 = prmt7632(xu, yu), h1 = prmt7632(zu, wu);
                float l0 = v.x - __uint_as_float(xu & 0xFFFF0000u);
                float l1 = v.y - __uint_as_float(yu & 0xFFFF0000u);
                float l2 = v.z - __uint_as_float(zu & 0xFFFF0000u);
                float l3 = v.w - __uint_as_float(wu & 0xFFFF0000u);
                *(uint2*)(st + sbase + 16u * j)          = make_uint2(h0, h1);
                *(uint2*)(st + TILE_B + sbase + 16u * j) = make_uint2(cvt2(l1, l0), cvt2(l3, l2));
            }
            {
                float4 v = bv[j];
                uint32_t xu = __float_as_uint(v.x), yu = __float_as_uint(v.y);
                uint32_t zu = __float_as_uint(v.z), wu = __float_as_uint(v.w);
                uint32_t h0 = prmt7632(xu, yu), h1 = prmt7632(zu, wu);
                float l0 = v.x - __uint_as_float(xu & 0xFFFF0000u);
                float l1 = v.y - __uint_as_float(yu & 0xFFFF0000u);
                float l2 = v.z - __uint_as_float(zu & 0xFFFF0000u);
                float l3 = v.w - __uint_as_float(wu & 0xFFFF0000u);
                *(uint2*)(st + 2 * TILE_B + sbase + 16u * j) = make_uint2(h0, h1);
                *(uint2*)(st + 3 * TILE_B + sbase + 16u * j) = make_uint2(cvt2(l1, l0), cvt2(l3, l2));
            }
        }
        /* prefetch next stage */
        if (i + 1 < nch) {
            const float* Ag2 = Ag + (size_t)(i + 1) * BK;
            const float* Bg2 = Bg + (size_t)(i + 1) * BK;
#pragma unroll
            for (int j = 0; j < 4; j++) {
                av[j] = *(const float4*)(Ag2 + 8 * j);
                bv[j] = *(const float4*)(Bg2 + 8 * j);
            }
        }
        __syncthreads();

        const uint32_t bufb = sb + (uint32_t)(i & 1) * STAGE_B;
#pragma unroll
        for (int ks = 0; ks < 2; ks++) {
            uint32_t ah[4][4], al[4][4], bh[4][2], bl[4][2];
#pragma unroll
            for (int mt = 0; mt < 4; mt++) {
                uint32_t r = (uint32_t)(wm * 64 + mt * 16 + (lid & 15));
                uint32_t off = r * ROWB + (uint32_t)((ks * 2 + (lid >> 4)) * 16);
                ldsm4(ah[mt], bufb + off);
                ldsm4(al[mt], bufb + TILE_B + off);
            }
#pragma unroll
            for (int nt = 0; nt < 4; nt++) {
                uint32_t r = (uint32_t)(wn * 32 + nt * 8 + (lid & 7));
                uint32_t off = r * ROWB + (uint32_t)((ks * 2 + ((lid >> 3) & 1)) * 16);
                ldsm2(bh[nt], bufb + 2 * TILE_B + off);
                ldsm2(bl[nt], bufb + 3 * TILE_B + off);
            }
#pragma unroll
            for (int mt = 0; mt < 4; mt++)
#pragma unroll
                for (int nt = 0; nt < 4; nt++) {
                    mma16816(acc[mt][nt], ah[mt], bh[nt]);
                    mma16816(acc[mt][nt], ah[mt], bl[nt]);
                    mma16816(acc[mt][nt], al[mt], bh[nt]);
                }
        }
    }

    /* epilogue: regs -> padded smem -> coalesced gmem */
    __syncthreads();
    float* stg = (float*)sm;
    const float S = 0.044194173824159216f;   /* 1/sqrt(512) */
#pragma unroll
    for (int mt = 0; mt < 4; mt++)
#pragma unroll
        for (int nt = 0; nt < 4; nt++) {
            int r0 = wm * 64 + mt * 16 + (lid >> 2);
            int c0 = wn * 32 + nt * 8 + 2 * (lid & 3);
            float v0 = acc[mt][nt][0], v1 = acc[mt][nt][1];
            float v2 = acc[mt][nt][2], v3 = acc[mt][nt][3];
            if (MODE == 2) { v0 *= S; v1 *= S; v2 *= S; v3 *= S; }
            if (MODE == 1) {
                float b0 = sbias[c0], b1 = sbias[c0 + 1];
                v0 += b0; v1 += b1; v2 += b0; v3 += b1;
            }
            *(float2*)&stg[r0 * 132 + c0]       = make_float2(v0, v1);
            *(float2*)&stg[(r0 + 8) * 132 + c0] = make_float2(v2, v3);
        }
    __syncthreads();
    float* Cp = C + z * Cbs;
#pragma unroll
    for (int p = 0; p < 16; p++) {
        int r = p * 8 + wid;
        float4 v = *(float4*)&stg[r * 132 + lid * 4];
        *(float4*)&Cp[(size_t)(m0 + r) * ldc + n0 + lid * 4] = v;
    }
}

/* ================== GroupNorm -> seq layout [s, c] ================== */
__global__ __launch_bounds__(256) void gn_kernel(
    const float* __restrict__ x,
    const float* __restrict__ gamma,
    const float* __restrict__ beta)
{
    __shared__ float rs[256], rss[256];
    __shared__ float tile[16 * 257];
    __shared__ float sc[16], sh[16];
    const int g = blockIdx.x, n = g >> 5, grp = g & 31;
    const float* xp = x + ((size_t)n * CCH + (size_t)grp * CPG) * HW;
    float* op = g_seq + (size_t)n * HW * CCH;
    const int NE = CPG * HW;

    float s = 0.f, ss = 0.f;
    for (int i = threadIdx.x; i < NE; i += 256) {
        float v = xp[i];
        s += v; ss += v * v;
    }
    rs[threadIdx.x] = s; rss[threadIdx.x] = ss;
    __syncthreads();
    for (int o = 128; o > 0; o >>= 1) {
        if (threadIdx.x < o) {
            rs[threadIdx.x] += rs[threadIdx.x + o];
            rss[threadIdx.x] += rss[threadIdx.x + o];
        }
        __syncthreads();
    }
    const float mean = rs[0] * (1.0f / NE);
    const float var  = rss[0] * (1.0f / NE) - mean * mean;
    const float rstd = rsqrtf(var + 1e-5f);
    if (threadIdx.x < 16) {
        int ch = grp * 16 + threadIdx.x;
        float gm = gamma[ch];
        sc[threadIdx.x] = rstd * gm;
        sh[threadIdx.x] = beta[ch] - mean * rstd * gm;
    }
    __syncthreads();

    for (int s0 = 0; s0 < HW; s0 += 256) {
#pragma unroll
        for (int ch = 0; ch < 16; ch++)
            tile[ch * 257 + threadIdx.x] = xp[(size_t)ch * HW + s0 + threadIdx.x] * sc[ch] + sh[ch];
        __syncthreads();
        float* orow = op + (size_t)(s0 + threadIdx.x) * CCH + grp * 16;
#pragma unroll
        for (int c4 = 0; c4 < 4; c4++) {
            float4 v;
            v.x = tile[(c4 * 4 + 0) * 257 + threadIdx.x];
            v.y = tile[(c4 * 4 + 1) * 257 + threadIdx.x];
            v.z = tile[(c4 * 4 + 2) * 257 + threadIdx.x];
            v.w = tile[(c4 * 4 + 3) * 257 + threadIdx.x];
            *(float4*)(orow + c4 * 4) = v;
        }
        __syncthreads();
    }
}

/* ================== softmax rows of scores ================== */
__global__ __launch_bounds__(256) void softmax_rows()
{
    float* p = g_scores + (size_t)blockIdx.x * SEQ;
    __shared__ float red[256];

    float m = -1e30f;
    for (int i = threadIdx.x; i < SEQ; i += 256) m = fmaxf(m, p[i]);
    red[threadIdx.x] = m;
    __syncthreads();
    for (int o = 128; o > 0; o >>= 1) {
        if (threadIdx.x < o)
            red[threadIdx.x] = fmaxf(red[threadIdx.x], red[threadIdx.x + o]);
        __syncthreads();
    }
    m = red[0];
    __syncthreads();

    float s = 0.f;
    for (int i = threadIdx.x; i < SEQ; i += 256) {
        float e = __expf(p[i] - m);
        p[i] = e;
        s += e;
    }
    red[threadIdx.x] = s;
    __syncthreads();
    for (int o = 128; o > 0; o >>= 1) {
        if (threadIdx.x < o) red[threadIdx.x] += red[threadIdx.x + o];
        __syncthreads();
    }
    const float inv = 1.0f / red[0];
    for (int i = threadIdx.x; i < SEQ; i += 256) p[i] *= inv;
}

/* ================== V transpose: qkv[:,1024+c] -> vt[c][t] ================== */
__global__ __launch_bounds__(256) void transpose_v()
{
    __shared__ float tl[32][33];
    const int z = blockIdx.z;
    const int t0 = blockIdx.x * 32, c0 = blockIdx.y * 32;
    const float* q = g_qkv + (size_t)z * HW * D3;
    float* vt = g_vt + (size_t)z * CCH * HW;
    const int tx = threadIdx.x, ty = threadIdx.y;
#pragma unroll
    for (int i = 0; i < 4; i++)
        tl[ty + i * 8][tx] = q[(size_t)(t0 + ty + i * 8) * D3 + 1024 + c0 + tx];
    __syncthreads();
#pragma unroll
    for (int i = 0; i < 4; i++)
        vt[(size_t)(c0 + ty + i * 8) * HW + t0 + tx] = tl[tx][ty + i * 8];
}

/* ================== final: out[c][s] = proj[s][c] + b_out[c] + x[c][s] ================== */
__global__ __launch_bounds__(256) void final_epilogue(
    const float* __restrict__ x, const float* __restrict__ b_out,
    float* __restrict__ out)
{
    __shared__ float tl[32][33];
    const int z = blockIdx.z;
    const int s0 = blockIdx.x * 32, c0 = blockIdx.y * 32;
    const float* pr = g_proj + (size_t)z * HW * CCH;
    const float* xp = x + (size_t)z * CCH * HW;
    float* op = out + (size_t)z * CCH * HW;
    const int tx = threadIdx.x, ty = threadIdx.y;
#pragma unroll
    for (int i = 0; i < 4; i++)
        tl[ty + i * 8][tx] = pr[(size_t)(s0 + ty + i * 8) * CCH + c0 + tx];
    __syncthreads();
#pragma unroll
    for (int i = 0; i < 4; i++) {
        int c = c0 + ty + i * 8;
        op[(size_t)c * HW + s0 + tx] =
            tl[tx][ty + i * 8] + b_out[c] + xp[(size_t)c * HW + s0 + tx];
    }
}

/* ================== launch ================== */
extern "C" void kernel_launch(void* const* d_in, const int* in_sizes, int n_in,
                              void* d_out, int out_size)
{
    const float* x     = (const float*)d_in[0];
    const float* gns   = (const float*)d_in[1];
    const float* gnb   = (const float*)d_in[2];
    const float* w_in  = (const float*)d_in[3];
    const float* b_in  = (const float*)d_in[4];
    const float* w_out = (const float*)d_in[5];
    const float* b_out = (const float*)d_in[6];
    float* out = (float*)d_out;

    float *seq_p, *qkv_p, *sc_p, *vt_p, *att_p, *proj_p;
    cudaGetSymbolAddress((void**)&seq_p,  g_seq);
    cudaGetSymbolAddress((void**)&qkv_p,  g_qkv);
    cudaGetSymbolAddress((void**)&sc_p,   g_scores);
    cudaGetSymbolAddress((void**)&vt_p,   g_vt);
    cudaGetSymbolAddress((void**)&att_p,  g_att);
    cudaGetSymbolAddress((void**)&proj_p, g_proj);

    cudaFuncSetAttribute(gemm_mma<0>, cudaFuncAttributeMaxDynamicSharedMemorySize, GEMM_SMEM);
    cudaFuncSetAttribute(gemm_mma<1>, cudaFuncAttributeMaxDynamicSharedMemorySize, GEMM_SMEM);
    cudaFuncSetAttribute(gemm_mma<2>, cudaFuncAttributeMaxDynamicSharedMemorySize, GEMM_SMEM);

    /* 1. GroupNorm -> g_seq [z][s][c] */
    gn_kernel<<<NB * NGRP, 256>>>(x, gns, gnb);

    /* 2. QKV: qkv[s,d] = seq[s,:] . w_in[d,:] + b_in[d] */
    gemm_mma<1><<<dim3(D3 / BN, HW / BM, NB), 256, GEMM_SMEM>>>(
        seq_p, w_in, qkv_p, b_in, CCH, CCH, CCH, D3,
        (size_t)HW * CCH, 0, (size_t)HW * D3);

    /* 3. scores[s,t] = scale * q[s,:] . k[t,:] */
    gemm_mma<2><<<dim3(SEQ / BN, SEQ / BM, NB), 256, GEMM_SMEM>>>(
        qkv_p, qkv_p + CCH, sc_p, nullptr, CCH, D3, D3, SEQ,
        (size_t)HW * D3, (size_t)HW * D3, (size_t)SEQ * SEQ);

    /* 4. softmax */
    softmax_rows<<<NB * SEQ, 256>>>();

    /* 5. V transpose -> vt[c][t] */
    transpose_v<<<dim3(HW / 32, CCH / 32, NB), dim3(32, 8)>>>();

    /* 6. att[s,c] = P[s,:] . vt[c,:] */
    gemm_mma<0><<<dim3(CCH / BN, HW / BM, NB), 256, GEMM_SMEM>>>(
        sc_p, vt_p, att_p, nullptr, SEQ, SEQ, HW, CCH,
        (size_t)SEQ * SEQ, (size_t)CCH * HW, (size_t)HW * CCH);

    /* 7. proj[s,c'] = att[s,:] . w_out[c',:] */
    gemm_mma<0><<<dim3(CCH / BN, HW / BM, NB), 256, GEMM_SMEM>>>(
        att_p, w_out, proj_p, nullptr, CCH, CCH, CCH, CCH,
        (size_t)HW * CCH, 0, (size_t)HW * CCH);

    /* 8. out = proj^T + b_out + x */
    final_epilogue<<<dim3(HW / 32, CCH / 32, NB), dim3(32, 8)>>>(x, b_out, out);
}

// round 4
// speedup vs baseline: 2.9375x; 1.3472x over previous
#include <cuda_runtime.h>
#include <cuda_fp16.h>
#include <cstdint>
#include <math.h>

#define NB    4
#define CCH   512
#define HW    4096
#define NGRP  32
#define CPG   16
#define D3    1536
#define SEQ   4096
#define BM    128
#define BN    128
#define BK    32
#define HWC2  (HW * CCH / 2)          /* u32 per batch for [s][512] fp16 */

/* ---------------- scratch ---------------- */
__device__ uint32_t g_sh[(size_t)NB * HWC2];        /* seq hi fp16   */
__device__ uint32_t g_sl[(size_t)NB * HWC2];        /* seq lo fp16   */
__device__ uint32_t g_wi[(size_t)D3 * CCH / 2];     /* w_in fp16     */
__device__ uint32_t g_wo[(size_t)CCH * CCH / 2];    /* w_out fp16    */
__device__ uint32_t g_qh[(size_t)NB * HWC2];
__device__ uint32_t g_ql[(size_t)NB * HWC2];
__device__ uint32_t g_k [(size_t)NB * HWC2];
__device__ uint32_t g_v [(size_t)NB * HWC2];
__device__ float    g_scores[(size_t)NB * SEQ * SEQ];
__device__ uint32_t g_ph[(size_t)NB * SEQ * SEQ / 2];
__device__ uint32_t g_pl[(size_t)NB * SEQ * SEQ / 2];
__device__ uint32_t g_ah[(size_t)NB * HWC2];
__device__ uint32_t g_al[(size_t)NB * HWC2];

/* ---------------- helpers ---------------- */
__device__ __forceinline__ uint32_t smem_u32(const void* p) {
    uint32_t a;
    asm("{ .reg .u64 t; cvta.to.shared.u64 t, %1; cvt.u32.u64 %0, t; }"
        : "=r"(a) : "l"(p));
    return a;
}
__device__ __forceinline__ uint32_t cvtf16x2(float hi, float lo) {
    uint32_t d;
    asm("cvt.rn.f16x2.f32 %0, %1, %2;" : "=r"(d) : "f"(hi), "f"(lo));
    return d;
}
__device__ __forceinline__ float2 unpack_h2(uint32_t u) {
    __half2 h = *reinterpret_cast<__half2*>(&u);
    return make_float2(__low2float(h), __high2float(h));
}
__device__ __forceinline__ void split_pair(float v0, float v1,
                                           uint32_t& hp, uint32_t& lp) {
    hp = cvtf16x2(v1, v0);
    float2 h = unpack_h2(hp);
    lp = cvtf16x2(v1 - h.y, v0 - h.x);
}
__device__ __forceinline__ void cpa16(uint32_t dst, const void* src) {
    asm volatile("cp.async.cg.shared.global [%0], [%1], 16;"
                 :: "r"(dst), "l"(src) : "memory");
}
__device__ __forceinline__ void ldsm4(uint32_t* r, uint32_t addr) {
    asm volatile("ldmatrix.sync.aligned.m8n8.x4.shared.b16 {%0,%1,%2,%3}, [%4];"
        : "=r"(r[0]), "=r"(r[1]), "=r"(r[2]), "=r"(r[3]) : "r"(addr));
}
__device__ __forceinline__ void ldsm2(uint32_t* r, uint32_t addr) {
    asm volatile("ldmatrix.sync.aligned.m8n8.x2.shared.b16 {%0,%1}, [%2];"
        : "=r"(r[0]), "=r"(r[1]) : "r"(addr));
}
__device__ __forceinline__ void ldsm2t(uint32_t* r, uint32_t addr) {
    asm volatile("ldmatrix.sync.aligned.m8n8.x2.trans.shared.b16 {%0,%1}, [%2];"
        : "=r"(r[0]), "=r"(r[1]) : "r"(addr));
}
__device__ __forceinline__ void mmaf16(float* c, const uint32_t* a, const uint32_t* b) {
    asm volatile("mma.sync.aligned.m16n8k16.row.col.f32.f16.f16.f32 "
        "{%0,%1,%2,%3}, {%4,%5,%6,%7}, {%8,%9}, {%0,%1,%2,%3};"
        : "+f"(c[0]), "+f"(c[1]), "+f"(c[2]), "+f"(c[3])
        : "r"(a[0]), "r"(a[1]), "r"(a[2]), "r"(a[3]), "r"(b[0]), "r"(b[1]));
}

#define ASZ 10240                      /* 128 rows x 80B */
#define GEMM_SMEM 69632

/* ============ 2-term fp16 GEMM: C[M,N] = (Ah+Al)[M,K] . B[N,K]^T ============
 * MODE 0: QKV  (+bias, route: n0<512 -> q split, <1024 -> k single, else v single)
 * MODE 1: scores (*1/sqrt(512), fp32 out)
 * MODE 2: PV   (att split out)
 * MODE 3: proj (fp32, +b_out +x residual, transposed store to d_out)
 * TB: B stored [k][n] (PV: V[t][c]) loaded via ldmatrix.trans
 */
template <int MODE, bool TB>
__global__ __launch_bounds__(256, 1)
void gemm_f16(const uint32_t* __restrict__ Ah, const uint32_t* __restrict__ Al,
              const uint32_t* __restrict__ Bg,
              void* __restrict__ o0, void* __restrict__ o1,
              void* __restrict__ o2, void* __restrict__ o3,
              const float* __restrict__ bias, const float* __restrict__ resid,
              int K, int ldaB, int ldbB, int ldc,
              size_t AzS, size_t BzS, size_t CzS)
{
    extern __shared__ char sm[];
    const uint32_t sb = smem_u32(sm);
    const int t = threadIdx.x, wid = t >> 5, lid = t & 31;
    const int wm = wid >> 2, wn = wid & 3;
    const int m0 = blockIdx.y * BM, n0 = blockIdx.x * BN, z = blockIdx.z;

    const int BSZ = TB ? 32 * 272 : ASZ;
    const int STG = 2 * ASZ + BSZ;

    const char* Ahp = (const char*)(Ah + z * AzS);
    const char* Alp = (const char*)(Al + z * AzS);
    const char* Bp  = (const char*)(Bg + z * BzS);

    float acc[4][4][4];
#pragma unroll
    for (int a = 0; a < 4; a++)
#pragma unroll
        for (int b = 0; b < 4; b++)
#pragma unroll
            for (int q = 0; q < 4; q++) acc[a][b][q] = 0.f;

    auto load_stage = [&](int i, int buf) {
        uint32_t d = sb + (uint32_t)buf * STG;
#pragma unroll
        for (int rep = 0; rep < 2; rep++) {
            int cid = rep * 256 + t;
            int row = cid >> 2, ch = cid & 3;
            size_t ao = (size_t)(m0 + row) * ldaB + (size_t)i * 64 + ch * 16;
            cpa16(d + row * 80 + ch * 16, Ahp + ao);
            cpa16(d + ASZ + row * 80 + ch * 16, Alp + ao);
            if (!TB) {
                cpa16(d + 2 * ASZ + row * 80 + ch * 16,
                      Bp + (size_t)(n0 + row) * ldbB + (size_t)i * 64 + ch * 16);
            } else {
                int br = cid >> 4, bc = cid & 15;
                cpa16(d + 2 * ASZ + br * 272 + bc * 16,
                      Bp + (size_t)(i * 32 + br) * ldbB + (size_t)n0 * 2 + bc * 16);
            }
        }
        asm volatile("cp.async.commit_group;" ::: "memory");
    };

    const int nch = K / BK;
    load_stage(0, 0);
    for (int i = 0; i < nch; i++) {
        if (i + 1 < nch) {
            load_stage(i + 1, (i + 1) & 1);
            asm volatile("cp.async.wait_group 1;" ::: "memory");
        } else {
            asm volatile("cp.async.wait_group 0;" ::: "memory");
        }
        __syncthreads();
        const uint32_t bb = sb + (uint32_t)(i & 1) * STG;
#pragma unroll
        for (int ks = 0; ks < 2; ks++) {
            uint32_t ah[4][4], al[4][4], bf[4][2];
#pragma unroll
            for (int mt = 0; mt < 4; mt++) {
                uint32_t r = (uint32_t)(wm * 64 + mt * 16 + (lid & 15));
                uint32_t off = r * 80 + (uint32_t)((ks * 2 + (lid >> 4)) * 16);
                ldsm4(ah[mt], bb + off);
                ldsm4(al[mt], bb + ASZ + off);
            }
#pragma unroll
            for (int nt = 0; nt < 4; nt++) {
                if (!TB) {
                    uint32_t r = (uint32_t)(wn * 32 + nt * 8 + (lid & 7));
                    uint32_t off = r * 80 + (uint32_t)((ks * 2 + ((lid >> 3) & 1)) * 16);
                    ldsm2(bf[nt], bb + 2 * ASZ + off);
                } else {
                    uint32_t r = (uint32_t)(ks * 16 + (lid & 15));
                    uint32_t off = r * 272 + (uint32_t)((wn * 32 + nt * 8) * 2);
                    ldsm2t(bf[nt], bb + 2 * ASZ + off);
                }
            }
#pragma unroll
            for (int mt = 0; mt < 4; mt++)
#pragma unroll
                for (int nt = 0; nt < 4; nt++) {
                    mmaf16(acc[mt][nt], ah[mt], bf[nt]);
                    mmaf16(acc[mt][nt], al[mt], bf[nt]);
                }
        }
        __syncthreads();
    }

    /* ---------------- epilogues ---------------- */
    if (MODE == 1) {                      /* scores: *scale, fp32 */
        float* stg = (float*)sm;
        const float S = 0.044194173824159216f;
#pragma unroll
        for (int mt = 0; mt < 4; mt++)
#pragma unroll
            for (int nt = 0; nt < 4; nt++) {
                int r0 = wm * 64 + mt * 16 + (lid >> 2);
                int c0 = wn * 32 + nt * 8 + 2 * (lid & 3);
                *(float2*)&stg[r0 * 132 + c0] =
                    make_float2(acc[mt][nt][0] * S, acc[mt][nt][1] * S);
                *(float2*)&stg[(r0 + 8) * 132 + c0] =
                    make_float2(acc[mt][nt][2] * S, acc[mt][nt][3] * S);
            }
        __syncthreads();
        float* Cp = (float*)o0 + z * CzS;
#pragma unroll
        for (int p = 0; p < 16; p++) {
            int r = p * 8 + wid;
            float4 v = *(float4*)&stg[r * 132 + lid * 4];
            *(float4*)&Cp[(size_t)(m0 + r) * ldc + n0 + lid * 4] = v;
        }
    } else if (MODE == 3) {               /* proj: transpose + bias + residual */
        float* stg = (float*)sm;
#pragma unroll
        for (int mt = 0; mt < 4; mt++)
#pragma unroll
            for (int nt = 0; nt < 4; nt++) {
                int r0 = wm * 64 + mt * 16 + (lid >> 2);
                int c0 = wn * 32 + nt * 8 + 2 * (lid & 3);
                stg[r0 * 129 + c0]           = acc[mt][nt][0];
                stg[r0 * 129 + c0 + 1]       = acc[mt][nt][1];
                stg[(r0 + 8) * 129 + c0]     = acc[mt][nt][2];
                stg[(r0 + 8) * 129 + c0 + 1] = acc[mt][nt][3];
            }
        __syncthreads();
        float* op = (float*)o0 + z * CzS;
        const float* xp = resid + z * CzS;
#pragma unroll 8
        for (int p = 0; p < 64; p++) {
            int r = p * 2 + (t >> 7);     /* local c' */
            int s = t & 127;
            int c = n0 + r;
            float v = stg[s * 129 + r] + bias[c] +
                      xp[(size_t)c * HW + m0 + s];
            op[(size_t)c * HW + m0 + s] = v;
        }
    } else {                              /* MODE 0 / 2: fp16 (split) writes */
        uint32_t* stg = (uint32_t*)sm;
        uint32_t *dh, *dl = nullptr;
        int cb;
        bool split;
        if (MODE == 0) {
            if (n0 < 512)      { dh = (uint32_t*)o0 + (size_t)z * HWC2;
                                 dl = (uint32_t*)o1 + (size_t)z * HWC2;
                                 cb = n0 >> 1; split = true; }
            else if (n0 < 1024){ dh = (uint32_t*)o2 + (size_t)z * HWC2;
                                 cb = (n0 - 512) >> 1; split = false; }
            else               { dh = (uint32_t*)o3 + (size_t)z * HWC2;
                                 cb = (n0 - 1024) >> 1; split = false; }
        } else {
            dh = (uint32_t*)o0 + (size_t)z * HWC2;
            dl = (uint32_t*)o1 + (size_t)z * HWC2;
            cb = n0 >> 1; split = true;
        }
        float bb0[4], bb1[4];
#pragma unroll
        for (int nt = 0; nt < 4; nt++) {
            if (MODE == 0) {
                int c0 = wn * 32 + nt * 8 + 2 * (lid & 3);
                bb0[nt] = bias[n0 + c0];
                bb1[nt] = bias[n0 + c0 + 1];
            } else { bb0[nt] = 0.f; bb1[nt] = 0.f; }
        }
        for (int pass = 0; pass < (split ? 2 : 1); pass++) {
#pragma unroll
            for (int mt = 0; mt < 4; mt++)
#pragma unroll
                for (int nt = 0; nt < 4; nt++) {
                    int r0 = wm * 64 + mt * 16 + (lid >> 2);
                    int cu = ((wn * 32 + nt * 8) >> 1) + (lid & 3);
                    uint32_t hp, lp;
                    split_pair(acc[mt][nt][0] + bb0[nt], acc[mt][nt][1] + bb1[nt], hp, lp);
                    stg[r0 * 68 + cu] = pass ? lp : hp;
                    split_pair(acc[mt][nt][2] + bb0[nt], acc[mt][nt][3] + bb1[nt], hp, lp);
                    stg[(r0 + 8) * 68 + cu] = pass ? lp : hp;
                }
            __syncthreads();
            uint32_t* dst = pass ? dl : dh;
            int r = t >> 1, hb = (t & 1) * 32;
#pragma unroll
            for (int q2 = 0; q2 < 8; q2++) {
                uint4 v = *(uint4*)&stg[r * 68 + hb + q2 * 4];
                *(uint4*)&dst[(size_t)(m0 + r) * 256 + cb + hb + q2 * 4] = v;
            }
            __syncthreads();
        }
    }
}

/* ================== GroupNorm -> split fp16 seq [s][c] ================== */
__global__ __launch_bounds__(256) void gn_kernel(
    const float* __restrict__ x,
    const float* __restrict__ gamma,
    const float* __restrict__ beta)
{
    __shared__ float rs[256], rss[256];
    __shared__ float tile[16 * 257];
    __shared__ float sc[16], sh[16];
    const int g = blockIdx.x, n = g >> 5, grp = g & 31;
    const float* xp = x + ((size_t)n * CCH + (size_t)grp * CPG) * HW;
    uint32_t* oh = g_sh + (size_t)n * HWC2;
    uint32_t* ol = g_sl + (size_t)n * HWC2;
    const int NE = CPG * HW;

    float s = 0.f, ss = 0.f;
    for (int i = threadIdx.x; i < NE; i += 256) {
        float v = xp[i];
        s += v; ss += v * v;
    }
    rs[threadIdx.x] = s; rss[threadIdx.x] = ss;
    __syncthreads();
    for (int o = 128; o > 0; o >>= 1) {
        if (threadIdx.x < o) {
            rs[threadIdx.x] += rs[threadIdx.x + o];
            rss[threadIdx.x] += rss[threadIdx.x + o];
        }
        __syncthreads();
    }
    const float mean = rs[0] * (1.0f / NE);
    const float var  = rss[0] * (1.0f / NE) - mean * mean;
    const float rstd = rsqrtf(var + 1e-5f);
    if (threadIdx.x < 16) {
        int ch = grp * 16 + threadIdx.x;
        float gm = gamma[ch];
        sc[threadIdx.x] = rstd * gm;
        sh[threadIdx.x] = beta[ch] - mean * rstd * gm;
    }
    __syncthreads();

    for (int s0 = 0; s0 < HW; s0 += 256) {
#pragma unroll
        for (int ch = 0; ch < 16; ch++)
            tile[ch * 257 + threadIdx.x] = xp[(size_t)ch * HW + s0 + threadIdx.x] * sc[ch] + sh[ch];
        __syncthreads();
        size_t rowb = (size_t)(s0 + threadIdx.x) * 256 + grp * 8;
#pragma unroll
        for (int c4 = 0; c4 < 4; c4++) {
            float v0 = tile[(c4 * 4 + 0) * 257 + threadIdx.x];
            float v1 = tile[(c4 * 4 + 1) * 257 + threadIdx.x];
            float v2 = tile[(c4 * 4 + 2) * 257 + threadIdx.x];
            float v3 = tile[(c4 * 4 + 3) * 257 + threadIdx.x];
            uint32_t h0, l0, h1, l1;
            split_pair(v0, v1, h0, l0);
            split_pair(v2, v3, h1, l1);
            oh[rowb + c4 * 2]     = h0;
            oh[rowb + c4 * 2 + 1] = h1;
            ol[rowb + c4 * 2]     = l0;
            ol[rowb + c4 * 2 + 1] = l1;
        }
        __syncthreads();
    }
}

/* ================== round weights to fp16 ================== */
__global__ __launch_bounds__(256) void round_w(
    const float* __restrict__ src, uint32_t* __restrict__ dst, int npairs)
{
    int i = blockIdx.x * 256 + threadIdx.x;
    if (i < npairs) {
        float2 v = *(const float2*)&src[2 * i];
        dst[i] = cvtf16x2(v.y, v.x);
    }
}

/* ================== 2-pass softmax -> split fp16 P ================== */
__global__ __launch_bounds__(256) void softmax2()
{
    const float* p = g_scores + (size_t)blockIdx.x * SEQ;
    uint32_t* ph = g_ph + (size_t)blockIdx.x * 2048;
    uint32_t* pl = g_pl + (size_t)blockIdx.x * 2048;
    __shared__ float rm[256], rsum[256];
    const int t = threadIdx.x;

    float m = -1e30f, s = 0.f;
    for (int i = t; i < SEQ; i += 256) {
        float v = p[i];
        if (v > m) { s *= __expf(m - v); m = v; }
        s += __expf(v - m);
    }
    rm[t] = m; rsum[t] = s;
    __syncthreads();
    for (int o = 128; o > 0; o >>= 1) {
        if (t < o) {
            float m2 = rm[t + o], mx = fmaxf(rm[t], m2);
            rsum[t] = rsum[t] * __expf(rm[t] - mx) + rsum[t + o] * __expf(m2 - mx);
            rm[t] = mx;
        }
        __syncthreads();
    }
    const float M = rm[0], inv = 1.0f / rsum[0];

    for (int i = t; i < 2048; i += 256) {
        float2 v = *(const float2*)&p[2 * i];
        float e0 = __expf(v.x - M) * inv;
        float e1 = __expf(v.y - M) * inv;
        uint32_t hp, lp;
        split_pair(e0, e1, hp, lp);
        ph[i] = hp;
        pl[i] = lp;
    }
}

/* ================== launch ================== */
extern "C" void kernel_launch(void* const* d_in, const int* in_sizes, int n_in,
                              void* d_out, int out_size)
{
    const float* x     = (const float*)d_in[0];
    const float* gns   = (const float*)d_in[1];
    const float* gnb   = (const float*)d_in[2];
    const float* w_in  = (const float*)d_in[3];
    const float* b_in  = (const float*)d_in[4];
    const float* w_out = (const float*)d_in[5];
    const float* b_out = (const float*)d_in[6];
    float* out = (float*)d_out;

    uint32_t *sh, *sl, *wi, *wo, *qh, *ql, *kk, *vv, *ph, *pl, *ath, *atl;
    float* sc;
    cudaGetSymbolAddress((void**)&sh,  g_sh);
    cudaGetSymbolAddress((void**)&sl,  g_sl);
    cudaGetSymbolAddress((void**)&wi,  g_wi);
    cudaGetSymbolAddress((void**)&wo,  g_wo);
    cudaGetSymbolAddress((void**)&qh,  g_qh);
    cudaGetSymbolAddress((void**)&ql,  g_ql);
    cudaGetSymbolAddress((void**)&kk,  g_k);
    cudaGetSymbolAddress((void**)&vv,  g_v);
    cudaGetSymbolAddress((void**)&sc,  g_scores);
    cudaGetSymbolAddress((void**)&ph,  g_ph);
    cudaGetSymbolAddress((void**)&pl,  g_pl);
    cudaGetSymbolAddress((void**)&ath, g_ah);
    cudaGetSymbolAddress((void**)&atl, g_al);

    cudaFuncSetAttribute(gemm_f16<0, false>, cudaFuncAttributeMaxDynamicSharedMemorySize, GEMM_SMEM);
    cudaFuncSetAttribute(gemm_f16<1, false>, cudaFuncAttributeMaxDynamicSharedMemorySize, GEMM_SMEM);
    cudaFuncSetAttribute(gemm_f16<2, true >, cudaFuncAttributeMaxDynamicSharedMemorySize, GEMM_SMEM);
    cudaFuncSetAttribute(gemm_f16<3, false>, cudaFuncAttributeMaxDynamicSharedMemorySize, GEMM_SMEM);

    /* 1. GroupNorm -> split fp16 seq */
    gn_kernel<<<NB * NGRP, 256>>>(x, gns, gnb);

    /* 2. round weights */
    round_w<<<(D3 * CCH / 2 + 255) / 256, 256>>>(w_in, wi, D3 * CCH / 2);
    round_w<<<(CCH * CCH / 2 + 255) / 256, 256>>>(w_out, wo, CCH * CCH / 2);

    /* 3. QKV */
    gemm_f16<0, false><<<dim3(D3 / BN, HW / BM, NB), 256, GEMM_SMEM>>>(
        sh, sl, wi, qh, ql, kk, vv, b_in, nullptr,
        CCH, CCH * 2, CCH * 2, 0, HWC2, 0, 0);

    /* 4. scores = scale * q . k^T */
    gemm_f16<1, false><<<dim3(SEQ / BN, SEQ / BM, NB), 256, GEMM_SMEM>>>(
        qh, ql, kk, sc, nullptr, nullptr, nullptr, nullptr, nullptr,
        CCH, CCH * 2, CCH * 2, SEQ, HWC2, HWC2, (size_t)SEQ * SEQ);

    /* 5. softmax -> split P */
    softmax2<<<NB * SEQ, 256>>>();

    /* 6. att = P . V  (V via ldmatrix.trans) */
    gemm_f16<2, true><<<dim3(CCH / BN, SEQ / BM, NB), 256, GEMM_SMEM>>>(
        ph, pl, vv, ath, atl, nullptr, nullptr, nullptr, nullptr,
        SEQ, SEQ * 2, CCH * 2, 0, (size_t)SEQ * SEQ / 2, HWC2, 0);

    /* 7. proj + bias + residual -> d_out (transposed) */
    gemm_f16<3, false><<<dim3(CCH / BN, HW / BM, NB), 256, GEMM_SMEM>>>(
        ath, atl, wo, out, nullptr, nullptr, nullptr, b_out, x,
        CCH, CCH * 2, CCH * 2, HW, HWC2, 0, (size_t)CCH * HW);
}

// round 5
// speedup vs baseline: 4.5415x; 1.5461x over previous
#include <cuda_runtime.h>
#include <cuda_fp16.h>
#include <cstdint>
#include <math.h>

#define NB    4
#define CCH   512
#define HW    4096
#define NGRP  32
#define CPG   16
#define D3    1536
#define SEQ   4096
#define BM    128
#define BN    128
#define BK    32
#define HWC2  (HW * CCH / 2)

/* ---------------- scratch ---------------- */
__device__ uint32_t g_sh[(size_t)NB * HWC2];
__device__ uint32_t g_sl[(size_t)NB * HWC2];
__device__ uint32_t g_wi[(size_t)D3 * CCH / 2];
__device__ uint32_t g_wo[(size_t)CCH * CCH / 2];
__device__ uint32_t g_qh[(size_t)NB * HWC2];
__device__ uint32_t g_ql[(size_t)NB * HWC2];
__device__ uint32_t g_k [(size_t)NB * HWC2];
__device__ uint32_t g_v [(size_t)NB * HWC2];
__device__ float    g_scores[(size_t)NB * SEQ * SEQ];
__device__ uint32_t g_ph[(size_t)NB * SEQ * SEQ / 2];
__device__ uint32_t g_ah[(size_t)NB * HWC2];
__device__ uint32_t g_al[(size_t)NB * HWC2];

/* ---------------- helpers ---------------- */
__device__ __forceinline__ uint32_t smem_u32(const void* p) {
    uint32_t a;
    asm("{ .reg .u64 t; cvta.to.shared.u64 t, %1; cvt.u32.u64 %0, t; }"
        : "=r"(a) : "l"(p));
    return a;
}
__device__ __forceinline__ uint32_t cvtf16x2(float hi, float lo) {
    uint32_t d;
    asm("cvt.rn.f16x2.f32 %0, %1, %2;" : "=r"(d) : "f"(hi), "f"(lo));
    return d;
}
__device__ __forceinline__ float2 unpack_h2(uint32_t u) {
    __half2 h = *reinterpret_cast<__half2*>(&u);
    return make_float2(__low2float(h), __high2float(h));
}
__device__ __forceinline__ void split_pair(float v0, float v1,
                                           uint32_t& hp, uint32_t& lp) {
    hp = cvtf16x2(v1, v0);
    float2 h = unpack_h2(hp);
    lp = cvtf16x2(v1 - h.y, v0 - h.x);
}
__device__ __forceinline__ void cpa16(uint32_t dst, const void* src) {
    asm volatile("cp.async.cg.shared.global [%0], [%1], 16;"
                 :: "r"(dst), "l"(src) : "memory");
}
__device__ __forceinline__ void ldsm4(uint32_t* r, uint32_t addr) {
    asm volatile("ldmatrix.sync.aligned.m8n8.x4.shared.b16 {%0,%1,%2,%3}, [%4];"
        : "=r"(r[0]), "=r"(r[1]), "=r"(r[2]), "=r"(r[3]) : "r"(addr));
}
__device__ __forceinline__ void ldsm2(uint32_t* r, uint32_t addr) {
    asm volatile("ldmatrix.sync.aligned.m8n8.x2.shared.b16 {%0,%1}, [%2];"
        : "=r"(r[0]), "=r"(r[1]) : "r"(addr));
}
__device__ __forceinline__ void ldsm2t(uint32_t* r, uint32_t addr) {
    asm volatile("ldmatrix.sync.aligned.m8n8.x2.trans.shared.b16 {%0,%1}, [%2];"
        : "=r"(r[0]), "=r"(r[1]) : "r"(addr));
}
__device__ __forceinline__ void mmaf16(float* c, const uint32_t* a, const uint32_t* b) {
    asm volatile("mma.sync.aligned.m16n8k16.row.col.f32.f16.f16.f32 "
        "{%0,%1,%2,%3}, {%4,%5,%6,%7}, {%8,%9}, {%0,%1,%2,%3};"
        : "+f"(c[0]), "+f"(c[1]), "+f"(c[2]), "+f"(c[3])
        : "r"(a[0]), "r"(a[1]), "r"(a[2]), "r"(a[3]), "r"(b[0]), "r"(b[1]));
}

#define ASZ 10240                       /* 128 rows x 80B */
#define BSZT (32 * 272)                 /* trans-B tile: 32 rows x 272B */

/* ======== 2-term fp16 GEMM, 3-stage cp.async, 2 CTA/SM ========
 * C[M,N] = (Ah(+Al))[M,K] . B[N,K]^T
 * MODE 0: QKV (+bias, split-q/k/v routing)
 * MODE 1: scores (*1/sqrt(512), fp32)
 * MODE 2: PV (split att out)
 * MODE 3: proj (+b_out +x residual, transposed store)
 */
template <int MODE, bool TB, bool SPLITA>
__global__ __launch_bounds__(256, 2)
void gemm_f16(const uint32_t* __restrict__ Ah, const uint32_t* __restrict__ Al,
              const uint32_t* __restrict__ Bg,
              void* __restrict__ o0, void* __restrict__ o1,
              void* __restrict__ o2, void* __restrict__ o3,
              const float* __restrict__ bias, const float* __restrict__ resid,
              int K, int ldaB, int ldbB, int ldc,
              size_t AzS, size_t BzS, size_t CzS)
{
    extern __shared__ char sm[];
    const uint32_t sb = smem_u32(sm);
    const int t = threadIdx.x, wid = t >> 5, lid = t & 31;
    const int wm = wid >> 2, wn = wid & 3;
    const int m0 = blockIdx.y * BM, n0 = blockIdx.x * BN, z = blockIdx.z;

    const int NA  = SPLITA ? 2 : 1;
    const int BSZ = TB ? BSZT : ASZ;
    const int STG = NA * ASZ + BSZ;

    const char* Ahp = (const char*)(Ah + z * AzS);
    const char* Alp = SPLITA ? (const char*)(Al + z * AzS) : nullptr;
    const char* Bp  = (const char*)(Bg + z * BzS);

    float acc[4][4][4];
#pragma unroll
    for (int a = 0; a < 4; a++)
#pragma unroll
        for (int b = 0; b < 4; b++)
#pragma unroll
            for (int q = 0; q < 4; q++) acc[a][b][q] = 0.f;

    auto load_stage = [&](int i, int buf) {
        uint32_t d = sb + (uint32_t)buf * STG;
#pragma unroll
        for (int rep = 0; rep < 2; rep++) {
            int cid = rep * 256 + t;
            int row = cid >> 2, ch = cid & 3;
            size_t ao = (size_t)(m0 + row) * ldaB + (size_t)i * 64 + ch * 16;
            cpa16(d + row * 80 + ch * 16, Ahp + ao);
            if (SPLITA)
                cpa16(d + ASZ + row * 80 + ch * 16, Alp + ao);
            if (!TB) {
                cpa16(d + NA * ASZ + row * 80 + ch * 16,
                      Bp + (size_t)(n0 + row) * ldbB + (size_t)i * 64 + ch * 16);
            } else {
                int br = cid >> 4, bc = cid & 15;
                cpa16(d + NA * ASZ + br * 272 + bc * 16,
                      Bp + (size_t)(i * 32 + br) * ldbB + (size_t)n0 * 2 + bc * 16);
            }
        }
        asm volatile("cp.async.commit_group;" ::: "memory");
    };

    const int nch = K / BK;
    load_stage(0, 0);
    if (nch > 1) load_stage(1, 1);

    int buf = 0;
    for (int i = 0; i < nch; i++) {
        if (i + 1 < nch)
            asm volatile("cp.async.wait_group 1;" ::: "memory");
        else
            asm volatile("cp.async.wait_group 0;" ::: "memory");
        __syncthreads();
        if (i + 2 < nch) {
            int nb = buf + 2; if (nb >= 3) nb -= 3;
            load_stage(i + 2, nb);
        }
        const uint32_t bb = sb + (uint32_t)buf * STG;
#pragma unroll
        for (int ks = 0; ks < 2; ks++) {
            uint32_t ah[4][4], al[4][4], bf[4][2];
#pragma unroll
            for (int mt = 0; mt < 4; mt++) {
                uint32_t r = (uint32_t)(wm * 64 + mt * 16 + (lid & 15));
                uint32_t off = r * 80 + (uint32_t)((ks * 2 + (lid >> 4)) * 16);
                ldsm4(ah[mt], bb + off);
                if (SPLITA) ldsm4(al[mt], bb + ASZ + off);
            }
#pragma unroll
            for (int nt = 0; nt < 4; nt++) {
                if (!TB) {
                    uint32_t r = (uint32_t)(wn * 32 + nt * 8 + (lid & 7));
                    uint32_t off = r * 80 + (uint32_t)((ks * 2 + ((lid >> 3) & 1)) * 16);
                    ldsm2(bf[nt], bb + NA * ASZ + off);
                } else {
                    uint32_t r = (uint32_t)(ks * 16 + (lid & 15));
                    uint32_t off = r * 272 + (uint32_t)((wn * 32 + nt * 8) * 2);
                    ldsm2t(bf[nt], bb + NA * ASZ + off);
                }
            }
#pragma unroll
            for (int mt = 0; mt < 4; mt++)
#pragma unroll
                for (int nt = 0; nt < 4; nt++) {
                    mmaf16(acc[mt][nt], ah[mt], bf[nt]);
                    if (SPLITA) mmaf16(acc[mt][nt], al[mt], bf[nt]);
                }
        }
        buf++; if (buf == 3) buf = 0;
    }
    __syncthreads();

    /* ---------------- epilogues ---------------- */
    if (MODE == 1) {
        float* stg = (float*)sm;
        const float S = 0.044194173824159216f;
#pragma unroll
        for (int mt = 0; mt < 4; mt++)
#pragma unroll
            for (int nt = 0; nt < 4; nt++) {
                int r0 = wm * 64 + mt * 16 + (lid >> 2);
                int c0 = wn * 32 + nt * 8 + 2 * (lid & 3);
                *(float2*)&stg[r0 * 132 + c0] =
                    make_float2(acc[mt][nt][0] * S, acc[mt][nt][1] * S);
                *(float2*)&stg[(r0 + 8) * 132 + c0] =
                    make_float2(acc[mt][nt][2] * S, acc[mt][nt][3] * S);
            }
        __syncthreads();
        float* Cp = (float*)o0 + z * CzS;
#pragma unroll
        for (int p = 0; p < 16; p++) {
            int r = p * 8 + wid;
            float4 v = *(float4*)&stg[r * 132 + lid * 4];
            *(float4*)&Cp[(size_t)(m0 + r) * ldc + n0 + lid * 4] = v;
        }
    } else if (MODE == 3) {
        float* stg = (float*)sm;
#pragma unroll
        for (int mt = 0; mt < 4; mt++)
#pragma unroll
            for (int nt = 0; nt < 4; nt++) {
                int r0 = wm * 64 + mt * 16 + (lid >> 2);
                int c0 = wn * 32 + nt * 8 + 2 * (lid & 3);
                stg[r0 * 129 + c0]           = acc[mt][nt][0];
                stg[r0 * 129 + c0 + 1]       = acc[mt][nt][1];
                stg[(r0 + 8) * 129 + c0]     = acc[mt][nt][2];
                stg[(r0 + 8) * 129 + c0 + 1] = acc[mt][nt][3];
            }
        __syncthreads();
        float* op = (float*)o0 + z * CzS;
        const float* xp = resid + z * CzS;
#pragma unroll 8
        for (int p = 0; p < 64; p++) {
            int r = p * 2 + (t >> 7);
            int s = t & 127;
            int c = n0 + r;
            op[(size_t)c * HW + m0 + s] =
                stg[s * 129 + r] + bias[c] + xp[(size_t)c * HW + m0 + s];
        }
    } else {
        uint32_t* stg = (uint32_t*)sm;
        uint32_t *dh, *dl = nullptr;
        int cb;
        bool split;
        if (MODE == 0) {
            if (n0 < 512)      { dh = (uint32_t*)o0 + (size_t)z * HWC2;
                                 dl = (uint32_t*)o1 + (size_t)z * HWC2;
                                 cb = n0 >> 1; split = true; }
            else if (n0 < 1024){ dh = (uint32_t*)o2 + (size_t)z * HWC2;
                                 cb = (n0 - 512) >> 1; split = false; }
            else               { dh = (uint32_t*)o3 + (size_t)z * HWC2;
                                 cb = (n0 - 1024) >> 1; split = false; }
        } else {
            dh = (uint32_t*)o0 + (size_t)z * HWC2;
            dl = (uint32_t*)o1 + (size_t)z * HWC2;
            cb = n0 >> 1; split = true;
        }
        float bb0[4], bb1[4];
#pragma unroll
        for (int nt = 0; nt < 4; nt++) {
            if (MODE == 0) {
                int c0 = wn * 32 + nt * 8 + 2 * (lid & 3);
                bb0[nt] = bias[n0 + c0];
                bb1[nt] = bias[n0 + c0 + 1];
            } else { bb0[nt] = 0.f; bb1[nt] = 0.f; }
        }
        for (int pass = 0; pass < (split ? 2 : 1); pass++) {
#pragma unroll
            for (int mt = 0; mt < 4; mt++)
#pragma unroll
                for (int nt = 0; nt < 4; nt++) {
                    int r0 = wm * 64 + mt * 16 + (lid >> 2);
                    int cu = ((wn * 32 + nt * 8) >> 1) + (lid & 3);
                    uint32_t hp, lp;
                    split_pair(acc[mt][nt][0] + bb0[nt], acc[mt][nt][1] + bb1[nt], hp, lp);
                    stg[r0 * 68 + cu] = pass ? lp : hp;
                    split_pair(acc[mt][nt][2] + bb0[nt], acc[mt][nt][3] + bb1[nt], hp, lp);
                    stg[(r0 + 8) * 68 + cu] = pass ? lp : hp;
                }
            __syncthreads();
            uint32_t* dst = pass ? dl : dh;
            int r = t >> 1, hb = (t & 1) * 32;
#pragma unroll
            for (int q2 = 0; q2 < 8; q2++) {
                uint4 v = *(uint4*)&stg[r * 68 + hb + q2 * 4];
                *(uint4*)&dst[(size_t)(m0 + r) * 256 + cb + hb + q2 * 4] = v;
            }
            __syncthreads();
        }
    }
}

/* ================== GroupNorm -> split fp16 seq ================== */
__global__ __launch_bounds__(256) void gn_kernel(
    const float* __restrict__ x,
    const float* __restrict__ gamma,
    const float* __restrict__ beta)
{
    __shared__ float rs[256], rss[256];
    __shared__ float tile[16 * 257];
    __shared__ float sc[16], sh[16];
    const int g = blockIdx.x, n = g >> 5, grp = g & 31;
    const float* xp = x + ((size_t)n * CCH + (size_t)grp * CPG) * HW;
    uint32_t* oh = g_sh + (size_t)n * HWC2;
    uint32_t* ol = g_sl + (size_t)n * HWC2;
    const int NE = CPG * HW;

    float s = 0.f, ss = 0.f;
    for (int i = threadIdx.x; i < NE; i += 256) {
        float v = xp[i];
        s += v; ss += v * v;
    }
    rs[threadIdx.x] = s; rss[threadIdx.x] = ss;
    __syncthreads();
    for (int o = 128; o > 0; o >>= 1) {
        if (threadIdx.x < o) {
            rs[threadIdx.x] += rs[threadIdx.x + o];
            rss[threadIdx.x] += rss[threadIdx.x + o];
        }
        __syncthreads();
    }
    const float mean = rs[0] * (1.0f / NE);
    const float var  = rss[0] * (1.0f / NE) - mean * mean;
    const float rstd = rsqrtf(var + 1e-5f);
    if (threadIdx.x < 16) {
        int ch = grp * 16 + threadIdx.x;
        float gm = gamma[ch];
        sc[threadIdx.x] = rstd * gm;
        sh[threadIdx.x] = beta[ch] - mean * rstd * gm;
    }
    __syncthreads();

    for (int s0 = 0; s0 < HW; s0 += 256) {
#pragma unroll
        for (int ch = 0; ch < 16; ch++)
            tile[ch * 257 + threadIdx.x] = xp[(size_t)ch * HW + s0 + threadIdx.x] * sc[ch] + sh[ch];
        __syncthreads();
        size_t rowb = (size_t)(s0 + threadIdx.x) * 256 + grp * 8;
#pragma unroll
        for (int c4 = 0; c4 < 4; c4++) {
            float v0 = tile[(c4 * 4 + 0) * 257 + threadIdx.x];
            float v1 = tile[(c4 * 4 + 1) * 257 + threadIdx.x];
            float v2 = tile[(c4 * 4 + 2) * 257 + threadIdx.x];
            float v3 = tile[(c4 * 4 + 3) * 257 + threadIdx.x];
            uint32_t h0, l0, h1, l1;
            split_pair(v0, v1, h0, l0);
            split_pair(v2, v3, h1, l1);
            oh[rowb + c4 * 2]     = h0;
            oh[rowb + c4 * 2 + 1] = h1;
            ol[rowb + c4 * 2]     = l0;
            ol[rowb + c4 * 2 + 1] = l1;
        }
        __syncthreads();
    }
}

/* ================== round weights to fp16 ================== */
__global__ __launch_bounds__(256) void round_w(
    const float* __restrict__ src, uint32_t* __restrict__ dst, int npairs)
{
    int i = blockIdx.x * 256 + threadIdx.x;
    if (i < npairs) {
        float2 v = *(const float2*)&src[2 * i];
        dst[i] = cvtf16x2(v.y, v.x);
    }
}

/* ================== vectorized softmax -> single fp16 P ================== */
__global__ __launch_bounds__(256) void softmax2()
{
    const float4* p4 = (const float4*)(g_scores + (size_t)blockIdx.x * SEQ);
    uint2* ph2 = (uint2*)(g_ph + (size_t)blockIdx.x * 2048);
    __shared__ float rm[256], rsum[256];
    const int t = threadIdx.x;

    float m = -1e30f, s = 0.f;
#pragma unroll
    for (int it = 0; it < 4; it++) {
        float4 v = p4[t + it * 256];
        float lm = fmaxf(fmaxf(v.x, v.y), fmaxf(v.z, v.w));
        if (lm > m) { s *= __expf(m - lm); m = lm; }
        s += __expf(v.x - m) + __expf(v.y - m) + __expf(v.z - m) + __expf(v.w - m);
    }
    rm[t] = m; rsum[t] = s;
    __syncthreads();
    for (int o = 128; o > 0; o >>= 1) {
        if (t < o) {
            float m2 = rm[t + o], mx = fmaxf(rm[t], m2);
            rsum[t] = rsum[t] * __expf(rm[t] - mx) + rsum[t + o] * __expf(m2 - mx);
            rm[t] = mx;
        }
        __syncthreads();
    }
    const float M = rm[0], inv = 1.0f / rsum[0];

#pragma unroll
    for (int it = 0; it < 4; it++) {
        float4 v = p4[t + it * 256];
        float e0 = __expf(v.x - M) * inv;
        float e1 = __expf(v.y - M) * inv;
        float e2 = __expf(v.z - M) * inv;
        float e3 = __expf(v.w - M) * inv;
        ph2[t + it * 256] = make_uint2(cvtf16x2(e1, e0), cvtf16x2(e3, e2));
    }
}

/* ================== launch ================== */
extern "C" void kernel_launch(void* const* d_in, const int* in_sizes, int n_in,
                              void* d_out, int out_size)
{
    const float* x     = (const float*)d_in[0];
    const float* gns   = (const float*)d_in[1];
    const float* gnb   = (const float*)d_in[2];
    const float* w_in  = (const float*)d_in[3];
    const float* b_in  = (const float*)d_in[4];
    const float* w_out = (const float*)d_in[5];
    const float* b_out = (const float*)d_in[6];
    float* out = (float*)d_out;

    uint32_t *sh, *sl, *wi, *wo, *qh, *ql, *kk, *vv, *ph, *ath, *atl;
    float* sc;
    cudaGetSymbolAddress((void**)&sh,  g_sh);
    cudaGetSymbolAddress((void**)&sl,  g_sl);
    cudaGetSymbolAddress((void**)&wi,  g_wi);
    cudaGetSymbolAddress((void**)&wo,  g_wo);
    cudaGetSymbolAddress((void**)&qh,  g_qh);
    cudaGetSymbolAddress((void**)&ql,  g_ql);
    cudaGetSymbolAddress((void**)&kk,  g_k);
    cudaGetSymbolAddress((void**)&vv,  g_v);
    cudaGetSymbolAddress((void**)&sc,  g_scores);
    cudaGetSymbolAddress((void**)&ph,  g_ph);
    cudaGetSymbolAddress((void**)&ath, g_ah);
    cudaGetSymbolAddress((void**)&atl, g_al);

    const int SM_SPLIT = 3 * (3 * ASZ);          /* 92160 */
    const int SM_PV    = 3 * (ASZ + BSZT);       /* 56832 */

    cudaFuncSetAttribute(gemm_f16<0, false, true >, cudaFuncAttributeMaxDynamicSharedMemorySize, SM_SPLIT);
    cudaFuncSetAttribute(gemm_f16<1, false, true >, cudaFuncAttributeMaxDynamicSharedMemorySize, SM_SPLIT);
    cudaFuncSetAttribute(gemm_f16<2, true,  false>, cudaFuncAttributeMaxDynamicSharedMemorySize, SM_PV);
    cudaFuncSetAttribute(gemm_f16<3, false, true >, cudaFuncAttributeMaxDynamicSharedMemorySize, SM_SPLIT);

    gn_kernel<<<NB * NGRP, 256>>>(x, gns, gnb);
    round_w<<<(D3 * CCH / 2 + 255) / 256, 256>>>(w_in, wi, D3 * CCH / 2);
    round_w<<<(CCH * CCH / 2 + 255) / 256, 256>>>(w_out, wo, CCH * CCH / 2);

    /* QKV */
    gemm_f16<0, false, true><<<dim3(D3 / BN, HW / BM, NB), 256, SM_SPLIT>>>(
        sh, sl, wi, qh, ql, kk, vv, b_in, nullptr,
        CCH, CCH * 2, CCH * 2, 0, HWC2, 0, 0);

    /* scores */
    gemm_f16<1, false, true><<<dim3(SEQ / BN, SEQ / BM, NB), 256, SM_SPLIT>>>(
        qh, ql, kk, sc, nullptr, nullptr, nullptr, nullptr, nullptr,
        CCH, CCH * 2, CCH * 2, SEQ, HWC2, HWC2, (size_t)SEQ * SEQ);

    /* softmax -> fp16 P */
    softmax2<<<NB * SEQ, 256>>>();

    /* att = P . V (single-fp16 P, V via ldmatrix.trans) */
    gemm_f16<2, true, false><<<dim3(CCH / BN, SEQ / BM, NB), 256, SM_PV>>>(
        ph, nullptr, vv, ath, atl, nullptr, nullptr, nullptr, nullptr,
        SEQ, SEQ * 2, CCH * 2, 0, (size_t)SEQ * SEQ / 2, HWC2, 0);

    /* proj + bias + residual -> d_out */
    gemm_f16<3, false, true><<<dim3(CCH / BN, HW / BM, NB), 256, SM_SPLIT>>>(
        ath, atl, wo, out, nullptr, nullptr, nullptr, b_out, x,
        CCH, CCH * 2, CCH * 2, HW, HWC2, 0, (size_t)CCH * HW);
}